// round 6
// baseline (speedup 1.0000x reference)
#include <cuda_runtime.h>

// Scratch via __device__ globals (no allocations allowed).
__device__ float    g_part[8192];
__device__ unsigned g_count = 0;   // self-resetting ticket -> deterministic per call

// MUFU sqrt: single instruction, max rel err ~2^-23, sqrt(0)=0.
__device__ __forceinline__ float fsqrt_approx(float x) {
    float r;
    asm("sqrt.approx.f32 %0, %1;" : "=f"(r) : "f"(x));
    return r;
}

// Shapes fixed: [8,3,16,256,256] fp32 -> 384 planes of 256x256. Row = 64 float4.
// Each thread: 16-wide segment (4 float4) x 4 rows. ALL 20 loads (5 rows incl.
// the circular down-neighbor row) are issued up front into a register array so
// every warp has ~20 LDGs in flight before the first dependent use (MLP-bound fix).
// Lanes 0-15 of a warp tile one full 256-wide row, so the circular right-wrap
// value x[h, w+16] is the next lane's row[0].x -> one __shfl_sync, no extra load.
// TV magnitude: sqrt((x[h,w]-x[h,w+1])^2 + (x[h,w]-x[h+1,w])^2), circular.
__global__ void __launch_bounds__(128, 4) tv_fused_kernel(const float4* __restrict__ in4,
                                                          float* __restrict__ out,
                                                          double inv_n) {
    const int t     = blockIdx.x * 128 + threadIdx.x;
    const int plane = t >> 10;                // 1024 threads per 256x256 plane
    const int s     = t & 1023;
    const int w4    = (s & 15) << 2;          // float4 offset within row (0..60)
    const int h0    = (s >> 4) << 2;          // first row of this thread's 4-row strip

    const int lane = threadIdx.x & 31;
    const int nbr  = (lane & 16) | ((lane + 1) & 15);   // right neighbor in 16-lane row group
    const unsigned FULL = 0xFFFFFFFFu;

    const float4* __restrict__ p = in4 + (plane << 14);   // 16384 float4 per plane

    // ---- Load phase: 5 rows x 4 float4, all independent, front-batched ----
    float4 d[5][4];
    #pragma unroll
    for (int i = 0; i < 5; i++) {
        const int h = (h0 + i) & 255;         // wraps only for the last strip
        const float4* rp = p + (h << 6);
        d[i][0] = rp[w4];
        d[i][1] = rp[w4 + 1];
        d[i][2] = rp[w4 + 2];
        d[i][3] = rp[w4 + 3];
    }

    // ---- Compute phase ----
    float acc = 0.0f;
    #pragma unroll
    for (int i = 0; i < 4; i++) {
        const float nx = __shfl_sync(FULL, d[i][0].x, nbr);  // x[h0+i, w+16] (circular)

        #define TV_PROC(a, nxt, c)                                         \
        {                                                                  \
            float dx0 = a.x - a.y,   dy0 = a.x - c.x;                      \
            float dx1 = a.y - a.z,   dy1 = a.y - c.y;                      \
            float dx2 = a.z - a.w,   dy2 = a.z - c.z;                      \
            float dx3 = a.w - (nxt), dy3 = a.w - c.w;                      \
            acc += fsqrt_approx(fmaf(dx0, dx0, dy0 * dy0));                \
            acc += fsqrt_approx(fmaf(dx1, dx1, dy1 * dy1));                \
            acc += fsqrt_approx(fmaf(dx2, dx2, dy2 * dy2));                \
            acc += fsqrt_approx(fmaf(dx3, dx3, dy3 * dy3));                \
        }
        TV_PROC(d[i][0], d[i][1].x, d[i + 1][0])
        TV_PROC(d[i][1], d[i][2].x, d[i + 1][1])
        TV_PROC(d[i][2], d[i][3].x, d[i + 1][2])
        TV_PROC(d[i][3], nx,        d[i + 1][3])
        #undef TV_PROC
    }

    // Warp reduce (4 warps per block)
    #pragma unroll
    for (int o = 16; o > 0; o >>= 1)
        acc += __shfl_xor_sync(FULL, acc, o);

    __shared__ float warpsum[4];
    __shared__ bool  s_last;
    const int wid = threadIdx.x >> 5;
    if (lane == 0) warpsum[wid] = acc;
    if (threadIdx.x == 0) s_last = false;
    __syncthreads();

    if (threadIdx.x == 0) {
        float bsum = warpsum[0] + warpsum[1] + warpsum[2] + warpsum[3];
        g_part[blockIdx.x] = bsum;
        __threadfence();
        unsigned ticket = atomicAdd(&g_count, 1u);
        if (ticket == gridDim.x - 1) s_last = true;
    }
    __syncthreads();

    // Last block to arrive reduces all partials and writes the output.
    if (s_last) {
        double dsum = 0.0;
        for (int i = threadIdx.x; i < (int)gridDim.x; i += 128)
            dsum += (double)g_part[i];
        #pragma unroll
        for (int o = 16; o > 0; o >>= 1)
            dsum += __shfl_xor_sync(FULL, dsum, o);
        __shared__ double dws[4];
        if (lane == 0) dws[wid] = dsum;
        __syncthreads();
        if (threadIdx.x == 0) {
            double ssum = dws[0] + dws[1] + dws[2] + dws[3];
            out[0] = (float)(ssum * inv_n);
            g_count = 0;   // reset for next (graph-replayed) call
        }
    }
}

extern "C" void kernel_launch(void* const* d_in, const int* in_sizes, int n_in,
                              void* d_out, int out_size) {
    const float4* in4 = (const float4*)d_in[0];
    float* out = (float*)d_out;
    const long long n = in_sizes[0];              // 25,165,824
    // 384 planes * 1024 threads/plane = 393216 threads = 3072 blocks * 128
    const int threads = 128;
    const int blocks  = (int)(n / (threads * 64));  // 64 elems per thread -> 3072

    tv_fused_kernel<<<blocks, threads>>>(in4, out, 1.0 / (double)n);
}

// round 7
// speedup vs baseline: 1.2875x; 1.2875x over previous
#include <cuda_runtime.h>

// Scratch via __device__ globals (no allocations allowed).
__device__ float    g_part[8192];
__device__ unsigned g_count = 0;   // self-resetting ticket -> deterministic per call

// MUFU sqrt: single instruction, max rel err ~2^-23, sqrt(0)=0.
__device__ __forceinline__ float fsqrt_approx(float x) {
    float r;
    asm("sqrt.approx.f32 %0, %1;" : "=f"(r) : "f"(x));
    return r;
}

// Shapes fixed: [8,3,16,256,256] fp32 -> 384 planes of 256x256. Row = 64 float4.
// WARP-COALESCED layout: a warp owns 32 CONSECUTIVE float4 (half a row, 512B per
// LDG.128 = 4 cache lines, minimal L1 wavefronts) x an 8-row strip. Each thread
// holds one float4 per row for 9 rows (8 compute rows + circular down row),
// all loads front-batched. x-neighbor of the float4's last element comes from
// lane+1 via shfl_down; lane 31 loads the single boundary scalar per row.
// TV magnitude: sqrt((x[h,w]-x[h,w+1])^2 + (x[h,w]-x[h+1,w])^2), circular.
__global__ void __launch_bounds__(256) tv_fused_kernel(const float4* __restrict__ in4,
                                                       float* __restrict__ out,
                                                       double inv_n) {
    const unsigned FULL = 0xFFFFFFFFu;
    const int lane = threadIdx.x & 31;
    const int wid  = threadIdx.x >> 5;
    const int gw   = blockIdx.x * 8 + wid;    // global warp id
    const int plane = gw >> 6;                // 64 warps per 256x256 plane
    const int r     = gw & 63;
    const int q     = ((r & 1) << 5) + lane;  // float4 index within row (0..63)
    const int h0    = (r >> 1) << 3;          // first row of 8-row strip

    const float4* __restrict__ p4 = in4 + ((long)plane << 14);  // 16384 float4/plane
    const float*  __restrict__ pf = (const float*)p4;

    // ---- Load phase: 9 rows x 1 float4 per thread, front-batched ----
    float4 d[9];
    #pragma unroll
    for (int i = 0; i < 9; i++) {
        const int h = (h0 + i) & 255;         // wraps only for the last strip
        d[i] = p4[(h << 6) + q];
    }
    // Boundary scalar x[h, 4*(q+1)] for lane 31 only (1 line per warp per row).
    float nbr[8];
    if (lane == 31) {
        const int qn4 = ((q + 1) & 63) << 2;  // circular right wrap (float index)
        #pragma unroll
        for (int i = 0; i < 8; i++) {
            const int h = (h0 + i) & 255;
            nbr[i] = pf[(h << 8) + qn4];
        }
    }

    // ---- Compute phase ----
    float acc = 0.0f;
    #pragma unroll
    for (int i = 0; i < 8; i++) {
        float nx = __shfl_down_sync(FULL, d[i].x, 1);  // next float4's .x
        if (lane == 31) nx = nbr[i];

        const float4 a = d[i];
        const float4 c = d[i + 1];
        float dx0 = a.x - a.y, dy0 = a.x - c.x;
        float dx1 = a.y - a.z, dy1 = a.y - c.y;
        float dx2 = a.z - a.w, dy2 = a.z - c.z;
        float dx3 = a.w - nx,  dy3 = a.w - c.w;
        acc += fsqrt_approx(fmaf(dx0, dx0, dy0 * dy0));
        acc += fsqrt_approx(fmaf(dx1, dx1, dy1 * dy1));
        acc += fsqrt_approx(fmaf(dx2, dx2, dy2 * dy2));
        acc += fsqrt_approx(fmaf(dx3, dx3, dy3 * dy3));
    }

    // Warp reduce (8 warps per block)
    #pragma unroll
    for (int o = 16; o > 0; o >>= 1)
        acc += __shfl_xor_sync(FULL, acc, o);

    __shared__ float warpsum[8];
    __shared__ bool  s_last;
    if (lane == 0) warpsum[wid] = acc;
    if (threadIdx.x == 0) s_last = false;
    __syncthreads();

    if (threadIdx.x == 0) {
        float bsum = warpsum[0] + warpsum[1] + warpsum[2] + warpsum[3]
                   + warpsum[4] + warpsum[5] + warpsum[6] + warpsum[7];
        g_part[blockIdx.x] = bsum;
        __threadfence();
        unsigned ticket = atomicAdd(&g_count, 1u);
        if (ticket == gridDim.x - 1) s_last = true;
    }
    __syncthreads();

    // Last block to arrive reduces all partials and writes the output.
    if (s_last) {
        double dsum = 0.0;
        for (int i = threadIdx.x; i < (int)gridDim.x; i += 256)
            dsum += (double)g_part[i];
        #pragma unroll
        for (int o = 16; o > 0; o >>= 1)
            dsum += __shfl_xor_sync(FULL, dsum, o);
        __shared__ double dws[8];
        if (lane == 0) dws[wid] = dsum;
        __syncthreads();
        if (threadIdx.x == 0) {
            double ssum = dws[0] + dws[1] + dws[2] + dws[3]
                        + dws[4] + dws[5] + dws[6] + dws[7];
            out[0] = (float)(ssum * inv_n);
            g_count = 0;   // reset for next (graph-replayed) call
        }
    }
}

extern "C" void kernel_launch(void* const* d_in, const int* in_sizes, int n_in,
                              void* d_out, int out_size) {
    const float4* in4 = (const float4*)d_in[0];
    float* out = (float*)d_out;
    const long long n = in_sizes[0];              // 25,165,824
    // 384 planes * 64 warps/plane / 8 warps/block = 3072 blocks of 256 threads
    const int threads = 256;
    const int blocks  = (int)(n / (threads * 32));  // 32 elems per thread -> 3072

    tv_fused_kernel<<<blocks, threads>>>(in4, out, 1.0 / (double)n);
}